// round 15
// baseline (speedup 1.0000x reference)
#include <cuda_runtime.h>
#include <math.h>

#define B_ 16
#define S_ 2048
#define H_ 1024
#define F_ 1024
#define M_ (B_*S_)   /* 32768 rows */

// ---------------- scratch (no allocations allowed) ----------------
__device__ __align__(16) float g_C[(size_t)M_ * F_];   // relu(X@W_C+b)  [M,F]  128MB
__device__ __align__(16) float g_P[8 * M_];            // per-column-tile partial row sums
__device__ __align__(16) float g_alpha[M_];            // softmax weights
__device__ __align__(16) float g_q[B_ * F_];           // q = C^T @ item_weights
__device__ __align__(16) float g_g[B_ * F_];           // q@w1 + attn_bias (then h@w1 + attn_bias)

// =====================================================================
// Big GEMM, projection variant: out[m,n] = relu(sum_k X[m,k]*W[k,n] + bias[n])
// Tile 128x128, BK=16, 256 threads, 8x8 per-thread microtile.
// =====================================================================
__global__ __launch_bounds__(256) void gemm_proj(
    const float* __restrict__ X, const float* __restrict__ W,
    const float* __restrict__ bias, float* __restrict__ out)
{
    __shared__ float As[16][128];
    __shared__ float Bs[16][128];
    const int bm = blockIdx.y * 128;
    const int bn = blockIdx.x * 128;
    const int tid = threadIdx.x;
    const int tx = tid & 15, ty = tid >> 4;

    float acc[8][8];
#pragma unroll
    for (int i = 0; i < 8; i++)
#pragma unroll
        for (int j = 0; j < 8; j++) acc[i][j] = 0.f;

    for (int k0 = 0; k0 < 1024; k0 += 16) {
#pragma unroll
        for (int l = 0; l < 2; l++) {           // A tile: 128x16 -> transposed
            int i = tid + l * 256;
            int row = i >> 2, c4 = i & 3;
            float4 va = *(const float4*)&X[(size_t)(bm + row) * 1024 + k0 + c4 * 4];
            As[c4 * 4 + 0][row] = va.x;
            As[c4 * 4 + 1][row] = va.y;
            As[c4 * 4 + 2][row] = va.z;
            As[c4 * 4 + 3][row] = va.w;
        }
#pragma unroll
        for (int l = 0; l < 2; l++) {           // B tile: 16x128
            int i = tid + l * 256;
            int row = i >> 5, c4 = i & 31;
            *(float4*)&Bs[row][c4 * 4] =
                *(const float4*)&W[(size_t)(k0 + row) * F_ + bn + c4 * 4];
        }
        __syncthreads();
#pragma unroll
        for (int kk = 0; kk < 16; kk++) {
            float a[8], b[8]; float4 t;
            t = *(const float4*)&As[kk][ty * 8];     a[0]=t.x; a[1]=t.y; a[2]=t.z; a[3]=t.w;
            t = *(const float4*)&As[kk][ty * 8 + 4]; a[4]=t.x; a[5]=t.y; a[6]=t.z; a[7]=t.w;
            t = *(const float4*)&Bs[kk][tx * 8];     b[0]=t.x; b[1]=t.y; b[2]=t.z; b[3]=t.w;
            t = *(const float4*)&Bs[kk][tx * 8 + 4]; b[4]=t.x; b[5]=t.y; b[6]=t.z; b[7]=t.w;
#pragma unroll
            for (int i = 0; i < 8; i++)
#pragma unroll
                for (int j = 0; j < 8; j++)
                    acc[i][j] = fmaf(a[i], b[j], acc[i][j]);
        }
        __syncthreads();
    }

#pragma unroll
    for (int i = 0; i < 8; i++) {
        int r = bm + ty * 8 + i;
#pragma unroll
        for (int j = 0; j < 8; j++) {
            int n = bn + tx * 8 + j;
            out[(size_t)r * F_ + n] = fmaxf(acc[i][j] + bias[n], 0.f);
        }
    }
}

// =====================================================================
// Big GEMM, fused additive-attention variant:
// partial[m] (for this 128-col tile) = sum_{n in tile} tanh( (In@w2)[m,n] + g[b,n] ) * v[n]
// written to P[blockIdx.x*M_ + m]; the 8 column-tile partials are summed later.
// All 128 rows of a tile share one batch b (S_ % 128 == 0).
// =====================================================================
__global__ __launch_bounds__(256) void gemm_attn(
    const float* __restrict__ In, const float* __restrict__ W,
    const float* __restrict__ g, const float* __restrict__ v,
    float* __restrict__ P)
{
    __shared__ float As[16][128];
    __shared__ float Bs[16][128];
    __shared__ float red[128][17];
    const int bm = blockIdx.y * 128;
    const int bn = blockIdx.x * 128;
    const int tid = threadIdx.x;
    const int tx = tid & 15, ty = tid >> 4;
    const int b = bm / S_;

    float acc[8][8];
#pragma unroll
    for (int i = 0; i < 8; i++)
#pragma unroll
        for (int j = 0; j < 8; j++) acc[i][j] = 0.f;

    for (int k0 = 0; k0 < 1024; k0 += 16) {
#pragma unroll
        for (int l = 0; l < 2; l++) {
            int i = tid + l * 256;
            int row = i >> 2, c4 = i & 3;
            float4 va = *(const float4*)&In[(size_t)(bm + row) * 1024 + k0 + c4 * 4];
            As[c4 * 4 + 0][row] = va.x;
            As[c4 * 4 + 1][row] = va.y;
            As[c4 * 4 + 2][row] = va.z;
            As[c4 * 4 + 3][row] = va.w;
        }
#pragma unroll
        for (int l = 0; l < 2; l++) {
            int i = tid + l * 256;
            int row = i >> 5, c4 = i & 31;
            *(float4*)&Bs[row][c4 * 4] =
                *(const float4*)&W[(size_t)(k0 + row) * F_ + bn + c4 * 4];
        }
        __syncthreads();
#pragma unroll
        for (int kk = 0; kk < 16; kk++) {
            float a[8], bb[8]; float4 t;
            t = *(const float4*)&As[kk][ty * 8];     a[0]=t.x; a[1]=t.y; a[2]=t.z; a[3]=t.w;
            t = *(const float4*)&As[kk][ty * 8 + 4]; a[4]=t.x; a[5]=t.y; a[6]=t.z; a[7]=t.w;
            t = *(const float4*)&Bs[kk][tx * 8];     bb[0]=t.x; bb[1]=t.y; bb[2]=t.z; bb[3]=t.w;
            t = *(const float4*)&Bs[kk][tx * 8 + 4]; bb[4]=t.x; bb[5]=t.y; bb[6]=t.z; bb[7]=t.w;
#pragma unroll
            for (int i = 0; i < 8; i++)
#pragma unroll
                for (int j = 0; j < 8; j++)
                    acc[i][j] = fmaf(a[i], bb[j], acc[i][j]);
        }
        __syncthreads();
    }

    // fused epilogue: tanh(acc + g[b,n]) * v[n], reduce over the tile columns
    float rowsum[8];
#pragma unroll
    for (int i = 0; i < 8; i++) rowsum[i] = 0.f;
#pragma unroll
    for (int j = 0; j < 8; j++) {
        int n = bn + tx * 8 + j;
        float gn = g[b * F_ + n];
        float vn = v[n];
#pragma unroll
        for (int i = 0; i < 8; i++)
            rowsum[i] = fmaf(tanhf(acc[i][j] + gn), vn, rowsum[i]);
    }
#pragma unroll
    for (int i = 0; i < 8; i++) red[ty * 8 + i][tx] = rowsum[i];
    __syncthreads();
    if (tid < 128) {
        float s = 0.f;
#pragma unroll
        for (int t = 0; t < 16; t++) s += red[tid][t];
        P[(size_t)blockIdx.x * M_ + bm + tid] = s;
    }
}

// =====================================================================
// out[b,f] = sum_s In[b,s,f] * w[b,s]    (q and h computations)
// grid (F_/64, B_), 256 threads: 64 f-lanes x 4 S-slices of 512.
// =====================================================================
__global__ __launch_bounds__(256) void colreduce(
    const float* __restrict__ In, const float* __restrict__ w,
    float* __restrict__ out)
{
    const int b = blockIdx.y;
    const int tid = threadIdx.x;
    const int fl = tid & 63;
    const int slice = tid >> 6;
    const int f = blockIdx.x * 64 + fl;
    const float* base = In + ((size_t)b * S_ + (size_t)slice * 512) * F_ + f;
    const float* wb = w + b * S_ + slice * 512;
    float acc = 0.f;
#pragma unroll 8
    for (int s = 0; s < 512; s++) acc = fmaf(base[(size_t)s * F_], wb[s], acc);
    __shared__ float sh[4][64];
    sh[slice][fl] = acc;
    __syncthreads();
    if (slice == 0)
        out[b * F_ + f] = (sh[0][fl] + sh[1][fl]) + (sh[2][fl] + sh[3][fl]);
}

// =====================================================================
// out[b,n] = sum_k in[b,k]*w1[k,n] + bias[n]     (tiny [16,1024]x[1024,1024])
// grid (F_/128, B_), 128 threads.
// =====================================================================
__global__ __launch_bounds__(128) void small_gemm(
    const float* __restrict__ inp, const float* __restrict__ w1,
    const float* __restrict__ bias, float* __restrict__ out)
{
    const int b = blockIdx.y;
    const int n = blockIdx.x * 128 + threadIdx.x;
    __shared__ float sq[128];
    float acc = 0.f;
    for (int k0 = 0; k0 < F_; k0 += 128) {
        __syncthreads();
        sq[threadIdx.x] = inp[b * F_ + k0 + threadIdx.x];
        __syncthreads();
#pragma unroll 16
        for (int kk = 0; kk < 128; kk++)
            acc = fmaf(sq[kk], w1[(size_t)(k0 + kk) * F_ + n], acc);
    }
    out[b * F_ + n] = acc + bias[n];
}

// =====================================================================
// softmax over S per batch: alpha = softmax(sum_c P[c] + mask_add)
// one block per batch, 1024 threads, 2 elements each.
// =====================================================================
__global__ __launch_bounds__(1024) void softmax_k(
    const float* __restrict__ P, const float* __restrict__ mask,
    float* __restrict__ alpha)
{
    const int b = blockIdx.x, tid = threadIdx.x;
    __shared__ float sh[S_];
    __shared__ float red[32];
    __shared__ float s_bcast;

    float lv[2];
#pragma unroll
    for (int l = 0; l < 2; l++) {
        int s = tid + l * 1024;
        float vv = 0.f;
#pragma unroll
        for (int c = 0; c < 8; c++) vv += P[(size_t)c * M_ + b * S_ + s];
        vv += (1.f - mask[b * S_ + s]) * -10000.f;
        lv[l] = vv;
    }
    float m = fmaxf(lv[0], lv[1]);
#pragma unroll
    for (int o = 16; o; o >>= 1) m = fmaxf(m, __shfl_xor_sync(0xffffffffu, m, o));
    if ((tid & 31) == 0) red[tid >> 5] = m;
    __syncthreads();
    if (tid == 0) {
        float mm = red[0];
        for (int w = 1; w < 32; w++) mm = fmaxf(mm, red[w]);
        s_bcast = mm;
    }
    __syncthreads();
    m = s_bcast;
    float e0 = expf(lv[0] - m), e1 = expf(lv[1] - m);
    sh[tid] = e0; sh[tid + 1024] = e1;
    float sum = e0 + e1;
#pragma unroll
    for (int o = 16; o; o >>= 1) sum += __shfl_xor_sync(0xffffffffu, sum, o);
    if ((tid & 31) == 0) red[tid >> 5] = sum;
    __syncthreads();
    if (tid == 0) {
        float ss = 0.f;
        for (int w = 0; w < 32; w++) ss += red[w];
        s_bcast = ss;
    }
    __syncthreads();
    float inv = 1.f / s_bcast;
    alpha[b * S_ + tid]        = sh[tid] * inv;
    alpha[b * S_ + tid + 1024] = sh[tid + 1024] * inv;
}

// =====================================================================
// sparsemax over S per batch:
//   z = (sum_c P[c]) * sigmoid(x) + mask_add ;  p = max(z - tau, 0)
// bitonic sort (desc) + Hillis-Steele scan in SMEM, one block per batch.
// =====================================================================
__global__ __launch_bounds__(1024) void sparsemax_k(
    const float* __restrict__ P, const float* __restrict__ mask,
    const float* __restrict__ w1s, const float* __restrict__ w2s,
    const float* __restrict__ w3s, const int* __restrict__ layer_i,
    float* __restrict__ Lout)
{
    const int b = blockIdx.x, tid = threadIdx.x;
    __shared__ float z[S_];
    __shared__ float zs[S_];
    __shared__ float c0[S_];
    __shared__ float c1[S_];
    __shared__ float s_tau;
    __shared__ int redi[32];

    float a1 = w1s[0] * w1s[0], a2 = w2s[0] * w2s[0], a3 = w3s[0] * w3s[0];
    int li = layer_i[0];
    float x = (li == 0) ? (a3 - a2 - a1) : ((li == 1) ? (a3 - a2) : a3);
    float sig = 1.f / (1.f + expf(-x));

    for (int s = tid; s < S_; s += 1024) {
        float vv = 0.f;
#pragma unroll
        for (int c = 0; c < 8; c++) vv += P[(size_t)c * M_ + b * S_ + s];
        vv = vv * sig + (1.f - mask[b * S_ + s]) * -10000.f;
        z[s] = vv; zs[s] = vv;
    }
    __syncthreads();

    // bitonic sort, descending
    for (int k = 2; k <= S_; k <<= 1) {
        for (int j = k >> 1; j > 0; j >>= 1) {
            for (int i = tid; i < S_; i += 1024) {
                int ixj = i ^ j;
                if (ixj > i) {
                    bool desc = ((i & k) == 0);
                    float va = zs[i], vb = zs[ixj];
                    bool sw = desc ? (va < vb) : (va > vb);
                    if (sw) { zs[i] = vb; zs[ixj] = va; }
                }
            }
            __syncthreads();
        }
    }

    // inclusive scan of zs
    for (int s = tid; s < S_; s += 1024) c0[s] = zs[s];
    __syncthreads();
    float* src = c0; float* dst = c1;
    for (int off = 1; off < S_; off <<= 1) {
        for (int s = tid; s < S_; s += 1024)
            dst[s] = src[s] + ((s >= off) ? src[s - off] : 0.f);
        __syncthreads();
        float* t = src; src = dst; dst = t;
    }

    // support size
    int cnt = 0;
    for (int s = tid; s < S_; s += 1024) {
        float kf = (float)(s + 1);
        if (1.f + kf * zs[s] > src[s]) cnt++;
    }
#pragma unroll
    for (int o = 16; o; o >>= 1) cnt += __shfl_xor_sync(0xffffffffu, cnt, o);
    if ((tid & 31) == 0) redi[tid >> 5] = cnt;
    __syncthreads();
    if (tid == 0) {
        int ks = 0;
        for (int w = 0; w < 32; w++) ks += redi[w];
        s_tau = (src[ks - 1] - 1.f) / (float)ks;
    }
    __syncthreads();
    float tau = s_tau;
    for (int s = tid; s < S_; s += 1024)
        Lout[b * S_ + s] = fmaxf(z[s] - tau, 0.f);
}

// =====================================================================
extern "C" void kernel_launch(void* const* d_in, const int* in_sizes, int n_in,
                              void* d_out, int out_size)
{
    const float* mask  = (const float*)d_in[0];   // [B,S]
    const float* X     = (const float*)d_in[1];   // [B,S,H]
    const float* iw    = (const float*)d_in[2];   // [B,S,1]
    const float* W_C   = (const float*)d_in[3];   // [H,F]
    const float* b_C   = (const float*)d_in[4];   // [F]
    const float* W_A   = (const float*)d_in[5];   // [H,F]
    const float* b_A   = (const float*)d_in[6];   // [F]
    const float* w1    = (const float*)d_in[7];   // [F,F]
    const float* w2    = (const float*)d_in[8];   // [F,F]
    const float* abias = (const float*)d_in[9];   // [1,1,F]
    const float* v     = (const float*)d_in[10];  // [F,1]
    const float* w_1   = (const float*)d_in[11];
    const float* w_2   = (const float*)d_in[12];
    const float* w_3   = (const float*)d_in[13];
    const int*   li    = (const int*)d_in[14];
    // d_in[15] = proactive_masking (unused, eval path)

    float* out   = (float*)d_out;
    float* h_out = out;                     // [B,F,1]
    float* L_out = out + B_ * F_;           // [B,S,1]
    float* A_out = out + B_ * F_ + B_ * S_; // [B,S,F]

    void *pC, *pP, *pAlpha, *pQ, *pG;
    cudaGetSymbolAddress(&pC, g_C);
    cudaGetSymbolAddress(&pP, g_P);
    cudaGetSymbolAddress(&pAlpha, g_alpha);
    cudaGetSymbolAddress(&pQ, g_q);
    cudaGetSymbolAddress(&pG, g_g);
    float* C  = (float*)pC;
    float* Pp = (float*)pP;
    float* al = (float*)pAlpha;
    float* q  = (float*)pQ;
    float* g  = (float*)pG;

    dim3 ggrid(F_ / 128, M_ / 128);   // (8, 256)

    // 1) projections
    gemm_proj<<<ggrid, 256>>>(X, W_C, b_C, C);
    gemm_proj<<<ggrid, 256>>>(X, W_A, b_A, A_out);

    // 2) q = C^T @ item_weights ; g = q@w1 + attn_bias
    colreduce<<<dim3(F_ / 64, B_), 256>>>(C, iw, q);
    small_gemm<<<dim3(F_ / 128, B_), 128>>>(q, w1, abias, g);

    // 3) alpha_pre partials from fused C@w2 attention; softmax
    gemm_attn<<<ggrid, 256>>>(C, w2, g, v, Pp);
    softmax_k<<<B_, 1024>>>(Pp, mask, al);

    // 4) h = C^T @ alpha (output #1); g = h@w1 + attn_bias
    colreduce<<<dim3(F_ / 64, B_), 256>>>(C, al, h_out);
    small_gemm<<<dim3(F_ / 128, B_), 128>>>(h_out, w1, abias, g);

    // 5) L_pre partials from fused A@w2 attention; scale/mask/sparsemax (output #2)
    gemm_attn<<<ggrid, 256>>>(A_out, w2, g, v, Pp);
    sparsemax_k<<<B_, 1024>>>(Pp, mask, w_1, w_2, w_3, li, L_out);
}